// round 2
// baseline (speedup 1.0000x reference)
#include <cuda_runtime.h>

// Problem constants (fixed by the reference: x,y in f32[4,4096,128])
#define BATCH 4
#define NPTS  4096
#define DIM   128
#define TILE  128
#define LDSS  130   // smem row stride in floats: conflict-free LDS.64 (130 % 32 == 2)

#define INF_BITS 0x7f800000u

// Scratch (allocation-free rule: __device__ globals)
__device__ float    g_x2[BATCH * NPTS];
__device__ float    g_y2[BATCH * NPTS];
__device__ unsigned g_rowmin[BATCH * NPTS];  // min_m d2 per (b,n), as uint bits (nonneg floats)
__device__ unsigned g_colmin[BATCH * NPTS];  // min_n d2 per (b,m)

// ---------------------------------------------------------------------------
// Kernel 1: init min arrays to +inf; compute squared norms (one warp per row)
// ---------------------------------------------------------------------------
__global__ void hd_prep(const float* __restrict__ x, const float* __restrict__ y) {
    int gtid = blockIdx.x * blockDim.x + threadIdx.x;
    if (gtid < BATCH * NPTS) {
        g_rowmin[gtid] = INF_BITS;
        g_colmin[gtid] = INF_BITS;
    }
    int warp = gtid >> 5;
    int lane = gtid & 31;
    // 2*BATCH*NPTS = 32768 rows total; grid sized exactly for this
    const float* src = (warp < BATCH * NPTS)
                           ? x + (size_t)warp * DIM
                           : y + (size_t)(warp - BATCH * NPTS) * DIM;
    float4 v = ((const float4*)src)[lane];
    float s = v.x * v.x + v.y * v.y + v.z * v.z + v.w * v.w;
    #pragma unroll
    for (int o = 16; o > 0; o >>= 1) s += __shfl_xor_sync(0xffffffffu, s, o);
    if (lane == 0) {
        if (warp < BATCH * NPTS) g_x2[warp] = s;
        else                     g_y2[warp - BATCH * NPTS] = s;
    }
}

// ---------------------------------------------------------------------------
// Kernel 2: tiled dot-product GEMM (full K=128) with fused min epilogue.
// 256 threads, 128x128 tile, 8x8 per-thread strided sub-tile, f32x2 packed FMA.
// ---------------------------------------------------------------------------
extern __shared__ float smem[];

__global__ __launch_bounds__(256, 1)
void hd_main(const float* __restrict__ x, const float* __restrict__ y) {
    float*    xs   = smem;                       // [128][LDSS]
    float*    ys   = smem + TILE * LDSS;         // [128][LDSS]
    unsigned* redR = (unsigned*)(smem + 2 * TILE * LDSS);  // [128]
    unsigned* redC = redR + TILE;                           // [128]

    const int tid = threadIdx.x;
    const int b   = blockIdx.z;
    const int n0  = blockIdx.y * TILE;
    const int m0  = blockIdx.x * TILE;

    if (tid < TILE) redR[tid]        = INF_BITS;
    else            redC[tid - TILE] = INF_BITS;

    const float* xg = x + ((size_t)b * NPTS + n0) * DIM;
    const float* yg = y + ((size_t)b * NPTS + m0) * DIM;

    // Load phase: 128x128 fp32 each, coalesced 512B per warp per row,
    // stored as 2x STS.64 (row stride 130 keeps 8B alignment: 520%8==0).
    #pragma unroll
    for (int i = 0; i < 16; i++) {
        int idx = i * 256 + tid;
        int row = idx >> 5;
        int c4  = idx & 31;
        float4 vx = ((const float4*)(xg + (size_t)row * DIM))[c4];
        float4 vy = ((const float4*)(yg + (size_t)row * DIM))[c4];
        float* px = xs + row * LDSS + c4 * 4;
        ((float2*)px)[0] = make_float2(vx.x, vx.y);
        ((float2*)px)[1] = make_float2(vx.z, vx.w);
        float* py = ys + row * LDSS + c4 * 4;
        ((float2*)py)[0] = make_float2(vy.x, vy.y);
        ((float2*)py)[1] = make_float2(vy.z, vy.w);
    }
    __syncthreads();

    const int tx = tid & 15;   // m = tx + 16*j
    const int ty = tid >> 4;   // n = ty + 16*i

    unsigned long long acc[8][8];
    #pragma unroll
    for (int i = 0; i < 8; i++)
        #pragma unroll
        for (int j = 0; j < 8; j++) acc[i][j] = 0ull;

    // Mainloop: packed-k dot products. Even k -> low lane, odd k -> high lane.
    #pragma unroll 2
    for (int k = 0; k < DIM; k += 2) {
        unsigned long long a2[8], b2[8];
        #pragma unroll
        for (int i = 0; i < 8; i++)
            a2[i] = *(const unsigned long long*)(xs + (ty + 16 * i) * LDSS + k);
        #pragma unroll
        for (int j = 0; j < 8; j++)
            b2[j] = *(const unsigned long long*)(ys + (tx + 16 * j) * LDSS + k);
        #pragma unroll
        for (int i = 0; i < 8; i++)
            #pragma unroll
            for (int j = 0; j < 8; j++)
                asm("fma.rn.f32x2 %0, %1, %2, %0;"
                    : "+l"(acc[i][j]) : "l"(a2[i]), "l"(b2[j]));
    }

    // Epilogue: d2 = x2 + y2 - 2*dot, clamp >= 0, thread-local row/col mins.
    float x2v[8], y2v[8];
    #pragma unroll
    for (int i = 0; i < 8; i++) x2v[i] = g_x2[b * NPTS + n0 + ty + 16 * i];
    #pragma unroll
    for (int j = 0; j < 8; j++) y2v[j] = g_y2[b * NPTS + m0 + tx + 16 * j];

    float rmin[8], cmin[8];
    #pragma unroll
    for (int i = 0; i < 8; i++) rmin[i] = __uint_as_float(INF_BITS);
    #pragma unroll
    for (int j = 0; j < 8; j++) cmin[j] = __uint_as_float(INF_BITS);

    #pragma unroll
    for (int i = 0; i < 8; i++) {
        #pragma unroll
        for (int j = 0; j < 8; j++) {
            float lo, hi;
            asm("mov.b64 {%0,%1}, %2;" : "=f"(lo), "=f"(hi) : "l"(acc[i][j]));
            float d2 = fmaxf(fmaf(-2.0f, lo + hi, x2v[i] + y2v[j]), 0.0f);
            rmin[i] = fminf(rmin[i], d2);
            cmin[j] = fminf(cmin[j], d2);
        }
    }

    // Block-level min via smem atomics (spread addresses), then one global
    // atomicMin per row/col of the tile. uint ordering == float ordering (>=0).
    #pragma unroll
    for (int i = 0; i < 8; i++) atomicMin(redR + ty + 16 * i, __float_as_uint(rmin[i]));
    #pragma unroll
    for (int j = 0; j < 8; j++) atomicMin(redC + tx + 16 * j, __float_as_uint(cmin[j]));
    __syncthreads();

    if (tid < TILE) atomicMin(&g_rowmin[b * NPTS + n0 + tid], redR[tid]);
    else            atomicMin(&g_colmin[b * NPTS + m0 + (tid - TILE)], redC[tid - TILE]);
}

// ---------------------------------------------------------------------------
// Kernel 3: per-batch max over union(rowmin, colmin), sqrt, mean.
// ---------------------------------------------------------------------------
__global__ void hd_finalize(float* __restrict__ out) {
    __shared__ float s[256];
    int tid = threadIdx.x;
    float sum = 0.0f;
    for (int b = 0; b < BATCH; b++) {
        float mx = 0.0f;
        for (int i = tid; i < NPTS; i += 256) {
            mx = fmaxf(mx, __uint_as_float(g_rowmin[b * NPTS + i]));
            mx = fmaxf(mx, __uint_as_float(g_colmin[b * NPTS + i]));
        }
        s[tid] = mx;
        __syncthreads();
        for (int st = 128; st > 0; st >>= 1) {
            if (tid < st) s[tid] = fmaxf(s[tid], s[tid + st]);
            __syncthreads();
        }
        if (tid == 0) sum += sqrtf(s[0]);
        __syncthreads();
    }
    if (tid == 0) out[0] = sum * (1.0f / BATCH);
}

// ---------------------------------------------------------------------------
extern "C" void kernel_launch(void* const* d_in, const int* in_sizes, int n_in,
                              void* d_out, int out_size) {
    const float* x = (const float*)d_in[0];
    const float* y = (const float*)d_in[1];
    float* out = (float*)d_out;

    const int smem_bytes = (2 * TILE * LDSS + 2 * TILE) * (int)sizeof(float);
    (void)cudaFuncSetAttribute(hd_main, cudaFuncAttributeMaxDynamicSharedMemorySize, smem_bytes);

    // 2*BATCH*NPTS rows, one warp each -> 32768 warps -> 1,048,576 threads
    hd_prep<<<(2 * BATCH * NPTS * 32) / 256, 256>>>(x, y);

    dim3 grid(NPTS / TILE, NPTS / TILE, BATCH);  // (32, 32, 4)
    hd_main<<<grid, 256, smem_bytes>>>(x, y);

    hd_finalize<<<1, 256>>>(out);
}

// round 5
// speedup vs baseline: 2.9828x; 2.9828x over previous
#include <cuda_runtime.h>
#include <cuda_bf16.h>
#include <cstdint>

// Problem constants (fixed: x,y in f32[4,4096,128])
#define BATCH 4
#define NPTS  4096
#define DIM   128
#define INF_BITS 0x7f800000u

// bf16 split: each row stored as [hi(128) | lo(128)] -> K=256 GEMM reproduces
// the fp32 dot to ~2^-16 relative (lo*lo term included, adds accuracy).
#define KSPLIT 256
#define ROWB   512            // bytes per row in gmem (256 bf16)
#define SSTE   264            // smem row stride in bf16 elems (528 B, pad 8)
#define SSTB   528            // smem row stride bytes (== 4 banks mod 32: ldmatrix conflict-free)

// ---------------- global scratch (allocation-free rule) ----------------
__device__ __nv_bfloat16 g_Ax[BATCH * NPTS * KSPLIT];
__device__ __nv_bfloat16 g_By[BATCH * NPTS * KSPLIT];
__device__ float    g_x2[BATCH * NPTS];
__device__ float    g_y2[BATCH * NPTS];
__device__ unsigned g_rowmin[BATCH * NPTS];  // plain store (unique writer)
__device__ unsigned g_colmin[BATCH * NPTS];  // atomicMin accumulated

// ---------------- smem layout (bytes) ----------------
#define A_OFF     0            // 128 * 528 = 67584
#define B0_OFF    67584
#define B1_OFF    135168
#define REDC_OFF  202752       // 128 u32
#define REDR_OFF  203264       // 128 u32
#define SMEM_BYTES 203776

// ---------------- PTX helpers (all sm_80+/sm_100-safe) ----------------
__device__ __forceinline__ uint32_t smem_u32(const void* p) {
    uint32_t a;
    asm("{ .reg .u64 t; cvta.to.shared.u64 t, %1; cvt.u32.u64 %0, t; }" : "=r"(a) : "l"(p));
    return a;
}
__device__ __forceinline__ void cp_async16(uint32_t saddr, const void* g) {
    asm volatile("cp.async.cg.shared.global [%0], [%1], 16;" :: "r"(saddr), "l"(g));
}
#define CP_COMMIT() asm volatile("cp.async.commit_group;" ::: "memory")
#define CP_WAIT0()  asm volatile("cp.async.wait_group 0;" ::: "memory")

__device__ __forceinline__ void ldsm_x4(uint32_t* r, uint32_t addr) {
    asm volatile("ldmatrix.sync.aligned.m8n8.x4.shared.b16 {%0,%1,%2,%3}, [%4];"
                 : "=r"(r[0]), "=r"(r[1]), "=r"(r[2]), "=r"(r[3]) : "r"(addr));
}
__device__ __forceinline__ void ldsm_x2(uint32_t* r, uint32_t addr) {
    asm volatile("ldmatrix.sync.aligned.m8n8.x2.shared.b16 {%0,%1}, [%2];"
                 : "=r"(r[0]), "=r"(r[1]) : "r"(addr));
}
__device__ __forceinline__ void mma_bf16(float* c, const uint32_t* a, const uint32_t* b) {
    asm volatile("mma.sync.aligned.m16n8k16.row.col.f32.bf16.bf16.f32 "
                 "{%0,%1,%2,%3}, {%4,%5,%6,%7}, {%8,%9}, {%0,%1,%2,%3};"
                 : "+f"(c[0]), "+f"(c[1]), "+f"(c[2]), "+f"(c[3])
                 : "r"(a[0]), "r"(a[1]), "r"(a[2]), "r"(a[3]), "r"(b[0]), "r"(b[1]));
}

// ---------------------------------------------------------------------------
// Kernel 1: bf16 hi/lo split + fp32 squared norms + colmin init. Warp per row.
// ---------------------------------------------------------------------------
__global__ void hd_prep(const float* __restrict__ x, const float* __restrict__ y) {
    int gtid = blockIdx.x * blockDim.x + threadIdx.x;
    if (gtid < BATCH * NPTS) g_colmin[gtid] = INF_BITS;

    int warp = gtid >> 5;
    int lane = gtid & 31;
    bool isx = warp < BATCH * NPTS;
    int row = isx ? warp : warp - BATCH * NPTS;
    const float* src = (isx ? x : y) + (size_t)row * DIM;

    float4 v = ((const float4*)src)[lane];

    __nv_bfloat16 h0 = __float2bfloat16_rn(v.x);
    __nv_bfloat16 h1 = __float2bfloat16_rn(v.y);
    __nv_bfloat16 h2 = __float2bfloat16_rn(v.z);
    __nv_bfloat16 h3 = __float2bfloat16_rn(v.w);
    __nv_bfloat16 l0 = __float2bfloat16_rn(v.x - __bfloat162float(h0));
    __nv_bfloat16 l1 = __float2bfloat16_rn(v.y - __bfloat162float(h1));
    __nv_bfloat16 l2 = __float2bfloat16_rn(v.z - __bfloat162float(h2));
    __nv_bfloat16 l3 = __float2bfloat16_rn(v.w - __bfloat162float(h3));

    uint2 hw, lw;
    hw.x = (unsigned)__bfloat16_as_ushort(h0) | ((unsigned)__bfloat16_as_ushort(h1) << 16);
    hw.y = (unsigned)__bfloat16_as_ushort(h2) | ((unsigned)__bfloat16_as_ushort(h3) << 16);
    lw.x = (unsigned)__bfloat16_as_ushort(l0) | ((unsigned)__bfloat16_as_ushort(l1) << 16);
    lw.y = (unsigned)__bfloat16_as_ushort(l2) | ((unsigned)__bfloat16_as_ushort(l3) << 16);

    __nv_bfloat16* dst = (isx ? g_Ax : g_By) + (size_t)row * KSPLIT;
    ((uint2*)dst)[lane]         = hw;   // hi block
    ((uint2*)(dst + 128))[lane] = lw;   // lo block

    float s = v.x * v.x + v.y * v.y + v.z * v.z + v.w * v.w;
    #pragma unroll
    for (int o = 16; o > 0; o >>= 1) s += __shfl_xor_sync(0xffffffffu, s, o);
    if (lane == 0) {
        if (isx) g_x2[row] = s;
        else     g_y2[row] = s;
    }
}

// ---------------------------------------------------------------------------
// Kernel 2: persistent-A bf16 mma.sync GEMM (K=256) with fused min epilogue.
// 128 CTAs = 4 batches x 32 n-tiles; each streams 32 m-tiles (double-buffered).
// Warp layout: 8 warps = 2 (M) x 4 (N); warp tile 64x32.
// ---------------------------------------------------------------------------
extern __shared__ unsigned char smem_raw[];

__global__ __launch_bounds__(256, 1)
void hd_main() {
    unsigned char* sm = smem_raw;
    const uint32_t sbase = smem_u32(sm);
    const int tid = threadIdx.x;
    const int wid = tid >> 5;
    const int ln  = tid & 31;
    const int wm  = wid >> 2;        // 0..1  (M half)
    const int wn  = wid & 3;         // 0..3  (N quarter)
    const int b   = blockIdx.x >> 5;
    const int n0  = (blockIdx.x & 31) * 128;

    unsigned* redC = (unsigned*)(sm + REDC_OFF);
    unsigned* redR = (unsigned*)(sm + REDR_OFF);
    if (tid < 128) { redC[tid] = INF_BITS; redR[tid] = INF_BITS; }

    // ---- prologue: async-load A tile and B tile 0 ----
    {
        const unsigned char* asrc = (const unsigned char*)(g_Ax + (size_t)(b * NPTS + n0) * KSPLIT);
        const unsigned char* bsrc = (const unsigned char*)(g_By + (size_t)(b * NPTS) * KSPLIT);
        #pragma unroll
        for (int it = 0; it < 16; it++) {
            int idx = it * 256 + tid;          // 4096 chunks of 16B
            int row = idx >> 5, c = idx & 31;
            cp_async16(sbase + A_OFF  + row * SSTB + c * 16, asrc + (size_t)row * ROWB + c * 16);
            cp_async16(sbase + B0_OFF + row * SSTB + c * 16, bsrc + (size_t)row * ROWB + c * 16);
        }
        CP_COMMIT();
        CP_WAIT0();
    }
    __syncthreads();

    // x2 per thread: 8 rows (mi 0..3, k2 0..1)
    float x2v[4][2];
    #pragma unroll
    for (int mi = 0; mi < 4; mi++)
        #pragma unroll
        for (int k2 = 0; k2 < 2; k2++)
            x2v[mi][k2] = g_x2[b * NPTS + n0 + wm * 64 + mi * 16 + (ln >> 2) + k2 * 8];

    // ldmatrix base addresses (k-step adds 32 B each)
    uint32_t aaddr[4], baddr[4];
    #pragma unroll
    for (int mi = 0; mi < 4; mi++)
        aaddr[mi] = sbase + A_OFF + (wm * 64 + mi * 16 + (ln & 15)) * SSTB + ((ln >> 4) * 8) * 2;
    #pragma unroll
    for (int ni = 0; ni < 4; ni++)
        baddr[ni] = sbase + B0_OFF + (wn * 32 + ni * 8 + (ln & 7)) * SSTB + (((ln >> 3) & 1) * 8) * 2;

    float rm[8];   // running rowmin per thread (rows mi*2+k2), min over this lane's cols
    #pragma unroll
    for (int r = 0; r < 8; r++) rm[r] = __uint_as_float(INF_BITS);

    for (int t = 0; t < 32; t++) {
        // issue next B tile into the other buffer (overlaps this tile's compute)
        if (t < 31) {
            const unsigned char* bsrc =
                (const unsigned char*)(g_By + (size_t)(b * NPTS + (t + 1) * 128) * KSPLIT);
            uint32_t boff = sbase + (((t + 1) & 1) ? B1_OFF : B0_OFF);
            #pragma unroll
            for (int it = 0; it < 16; it++) {
                int idx = it * 256 + tid;
                int row = idx >> 5, c = idx & 31;
                cp_async16(boff + row * SSTB + c * 16, bsrc + (size_t)row * ROWB + c * 16);
            }
            CP_COMMIT();
        }

        // y2 for this tile's columns (8 per thread), prefetched early
        float y2v[4][2];
        #pragma unroll
        for (int ni = 0; ni < 4; ni++)
            #pragma unroll
            for (int e = 0; e < 2; e++)
                y2v[ni][e] = g_y2[b * NPTS + t * 128 + wn * 32 + ni * 8 + (ln & 3) * 2 + e];

        const uint32_t bsel = (t & 1) ? (B1_OFF - B0_OFF) : 0u;

        float acc[4][4][4];
        #pragma unroll
        for (int mi = 0; mi < 4; mi++)
            #pragma unroll
            for (int ni = 0; ni < 4; ni++)
                #pragma unroll
                for (int k = 0; k < 4; k++) acc[mi][ni][k] = 0.0f;

        // ---- mainloop: K=256 in 16 k-steps ----
        #pragma unroll
        for (int ks = 0; ks < 16; ks++) {
            uint32_t afr[4][4], bfr[4][2];
            #pragma unroll
            for (int mi = 0; mi < 4; mi++) ldsm_x4(afr[mi], aaddr[mi] + ks * 32);
            #pragma unroll
            for (int ni = 0; ni < 4; ni++) ldsm_x2(bfr[ni], baddr[ni] + bsel + ks * 32);
            #pragma unroll
            for (int mi = 0; mi < 4; mi++)
                #pragma unroll
                for (int ni = 0; ni < 4; ni++)
                    mma_bf16(acc[mi][ni], afr[mi], bfr[ni]);
        }

        // ---- epilogue: d2, rowmin (regs), colmin (shfl + smem atomics) ----
        float cmv[4][2];
        #pragma unroll
        for (int ni = 0; ni < 4; ni++)
            #pragma unroll
            for (int e = 0; e < 2; e++) cmv[ni][e] = __uint_as_float(INF_BITS);

        #pragma unroll
        for (int mi = 0; mi < 4; mi++)
            #pragma unroll
            for (int ni = 0; ni < 4; ni++)
                #pragma unroll
                for (int k = 0; k < 4; k++) {
                    int k2 = k >> 1, e = k & 1;
                    float d2 = fmaxf(fmaf(-2.0f, acc[mi][ni][k], x2v[mi][k2] + y2v[ni][e]), 0.0f);
                    rm[mi * 2 + k2] = fminf(rm[mi * 2 + k2], d2);
                    cmv[ni][e]      = fminf(cmv[ni][e], d2);
                }

        #pragma unroll
        for (int ni = 0; ni < 4; ni++)
            #pragma unroll
            for (int e = 0; e < 2; e++) {
                float v = cmv[ni][e];
                v = fminf(v, __shfl_xor_sync(0xffffffffu, v, 4));
                v = fminf(v, __shfl_xor_sync(0xffffffffu, v, 8));
                v = fminf(v, __shfl_xor_sync(0xffffffffu, v, 16));
                if (ln < 4)
                    atomicMin(&redC[wn * 32 + ni * 8 + ln * 2 + e], __float_as_uint(v));
            }
        __syncthreads();

        if (tid < 128) {
            atomicMin(&g_colmin[b * NPTS + t * 128 + tid], redC[tid]);
            redC[tid] = INF_BITS;
        }
        if (t < 31) CP_WAIT0();   // next B tile landed
        __syncthreads();
    }

    // ---- final rowmin: fold cols across lanes, then across the 4 N-warps ----
    #pragma unroll
    for (int r = 0; r < 8; r++) {
        float v = rm[r];
        v = fminf(v, __shfl_xor_sync(0xffffffffu, v, 1));
        v = fminf(v, __shfl_xor_sync(0xffffffffu, v, 2));
        if ((ln & 3) == 0) {
            int rowl = wm * 64 + (r >> 1) * 16 + (ln >> 2) + (r & 1) * 8;
            atomicMin(&redR[rowl], __float_as_uint(v));
        }
    }
    __syncthreads();
    if (tid < 128) g_rowmin[b * NPTS + n0 + tid] = redR[tid];
}

// ---------------------------------------------------------------------------
// Kernel 3: per-batch max over union(rowmin, colmin), sqrt, mean.
// ---------------------------------------------------------------------------
__global__ void hd_finalize(float* __restrict__ out) {
    __shared__ float s[256];
    int tid = threadIdx.x;
    float sum = 0.0f;
    for (int b = 0; b < BATCH; b++) {
        float mx = 0.0f;
        for (int i = tid; i < NPTS; i += 256) {
            mx = fmaxf(mx, __uint_as_float(g_rowmin[b * NPTS + i]));
            mx = fmaxf(mx, __uint_as_float(g_colmin[b * NPTS + i]));
        }
        s[tid] = mx;
        __syncthreads();
        for (int st = 128; st > 0; st >>= 1) {
            if (tid < st) s[tid] = fmaxf(s[tid], s[tid + st]);
            __syncthreads();
        }
        if (tid == 0) sum += sqrtf(s[0]);
        __syncthreads();
    }
    if (tid == 0) out[0] = sum * (1.0f / BATCH);
}

// ---------------------------------------------------------------------------
extern "C" void kernel_launch(void* const* d_in, const int* in_sizes, int n_in,
                              void* d_out, int out_size) {
    const float* x = (const float*)d_in[0];
    const float* y = (const float*)d_in[1];
    float* out = (float*)d_out;

    (void)cudaFuncSetAttribute(hd_main, cudaFuncAttributeMaxDynamicSharedMemorySize,
                               SMEM_BYTES);

    hd_prep<<<(2 * BATCH * NPTS * 32) / 256, 256>>>(x, y);
    hd_main<<<BATCH * 32, 256, SMEM_BYTES>>>();
    hd_finalize<<<1, 256>>>(out);
}

// round 6
// speedup vs baseline: 4.5370x; 1.5210x over previous
#include <cuda_runtime.h>
#include <cuda_fp16.h>
#include <cstdint>

// Problem constants (fixed: x,y in f32[4,4096,128])
#define BATCH 4
#define NPTS  4096
#define DIM   128
#define INF_BITS 0x7f800000u

// Single fp16 GEMM, K=128. fp16 rounding (2^-11) gives dot error ~5e-3 abs
// on d2 ~ 250 -> final rel err ~4e-5, better than the bf16 hi/lo block split.
#define ROWB   256            // bytes per row in gmem (128 fp16)
#define SSTB   272            // smem row stride bytes (68 words, 68%32==4: ldmatrix conflict-free)

// ---------------- global scratch (allocation-free rule) ----------------
__device__ __half  g_Ax[BATCH * NPTS * DIM];
__device__ __half  g_By[BATCH * NPTS * DIM];
__device__ float    g_x2[BATCH * NPTS];
__device__ float    g_y2[BATCH * NPTS];
__device__ unsigned g_rowmin[BATCH * NPTS];  // plain store (unique writer)
__device__ unsigned g_colmin[BATCH * NPTS];  // atomicMin accumulated

// ---------------- smem layout (bytes) ----------------
#define A_OFF     0            // 128 * 272 = 34816
#define B0_OFF    34816
#define B1_OFF    69632
#define REDC_OFF  104448       // 128 u32
#define REDR_OFF  104960       // 128 u32
#define SMEM_BYTES 105472

// ---------------- PTX helpers (sm_80+ / plain sm_100-safe) ----------------
__device__ __forceinline__ uint32_t smem_u32(const void* p) {
    uint32_t a;
    asm("{ .reg .u64 t; cvta.to.shared.u64 t, %1; cvt.u32.u64 %0, t; }" : "=r"(a) : "l"(p));
    return a;
}
__device__ __forceinline__ void cp_async16(uint32_t saddr, const void* g) {
    asm volatile("cp.async.cg.shared.global [%0], [%1], 16;" :: "r"(saddr), "l"(g));
}
#define CP_COMMIT() asm volatile("cp.async.commit_group;" ::: "memory")
#define CP_WAIT0()  asm volatile("cp.async.wait_group 0;" ::: "memory")

__device__ __forceinline__ void ldsm_x4(uint32_t* r, uint32_t addr) {
    asm volatile("ldmatrix.sync.aligned.m8n8.x4.shared.b16 {%0,%1,%2,%3}, [%4];"
                 : "=r"(r[0]), "=r"(r[1]), "=r"(r[2]), "=r"(r[3]) : "r"(addr));
}
__device__ __forceinline__ void ldsm_x2(uint32_t* r, uint32_t addr) {
    asm volatile("ldmatrix.sync.aligned.m8n8.x2.shared.b16 {%0,%1}, [%2];"
                 : "=r"(r[0]), "=r"(r[1]) : "r"(addr));
}
__device__ __forceinline__ void mma_f16(float* c, const uint32_t* a, const uint32_t* b) {
    asm volatile("mma.sync.aligned.m16n8k16.row.col.f32.f16.f16.f32 "
                 "{%0,%1,%2,%3}, {%4,%5,%6,%7}, {%8,%9}, {%0,%1,%2,%3};"
                 : "+f"(c[0]), "+f"(c[1]), "+f"(c[2]), "+f"(c[3])
                 : "r"(a[0]), "r"(a[1]), "r"(a[2]), "r"(a[3]), "r"(b[0]), "r"(b[1]));
}

// ---------------------------------------------------------------------------
// Kernel 1: fp16 convert + fp32 squared norms + colmin init. Warp per row.
// ---------------------------------------------------------------------------
__global__ void hd_prep(const float* __restrict__ x, const float* __restrict__ y) {
    int gtid = blockIdx.x * blockDim.x + threadIdx.x;
    if (gtid < BATCH * NPTS) g_colmin[gtid] = INF_BITS;

    int warp = gtid >> 5;
    int lane = gtid & 31;
    bool isx = warp < BATCH * NPTS;
    int row = isx ? warp : warp - BATCH * NPTS;
    const float* src = (isx ? x : y) + (size_t)row * DIM;

    float4 v = ((const float4*)src)[lane];

    __half2 p0 = __floats2half2_rn(v.x, v.y);
    __half2 p1 = __floats2half2_rn(v.z, v.w);
    uint2 pw;
    pw.x = *(unsigned*)&p0;
    pw.y = *(unsigned*)&p1;

    __half* dst = (isx ? g_Ax : g_By) + (size_t)row * DIM;
    ((uint2*)dst)[lane] = pw;

    float s = v.x * v.x + v.y * v.y + v.z * v.z + v.w * v.w;
    #pragma unroll
    for (int o = 16; o > 0; o >>= 1) s += __shfl_xor_sync(0xffffffffu, s, o);
    if (lane == 0) {
        if (isx) g_x2[row] = s;
        else     g_y2[row] = s;
    }
}

// ---------------------------------------------------------------------------
// Kernel 2: persistent-A fp16 mma.sync GEMM (K=128) with fused min epilogue.
// 128 CTAs = 4 batches x 32 n-tiles; each streams 32 m-tiles (double-buffered).
// Warp layout: 8 warps = 2 (M) x 4 (N); warp tile 64x32.
// ---------------------------------------------------------------------------
extern __shared__ unsigned char smem_raw[];

__global__ __launch_bounds__(256, 1)
void hd_main() {
    unsigned char* sm = smem_raw;
    const uint32_t sbase = smem_u32(sm);
    const int tid = threadIdx.x;
    const int wid = tid >> 5;
    const int ln  = tid & 31;
    const int wm  = wid >> 2;        // 0..1  (M half)
    const int wn  = wid & 3;         // 0..3  (N quarter)
    const int b   = blockIdx.x >> 5;
    const int n0  = (blockIdx.x & 31) * 128;

    unsigned* redC = (unsigned*)(sm + REDC_OFF);
    unsigned* redR = (unsigned*)(sm + REDR_OFF);
    if (tid < 128) { redC[tid] = INF_BITS; redR[tid] = INF_BITS; }

    // ---- prologue: async-load A tile and B tile 0 (32 KB each) ----
    {
        const unsigned char* asrc = (const unsigned char*)(g_Ax + (size_t)(b * NPTS + n0) * DIM);
        const unsigned char* bsrc = (const unsigned char*)(g_By + (size_t)(b * NPTS) * DIM);
        #pragma unroll
        for (int it = 0; it < 8; it++) {
            int idx = it * 256 + tid;          // 2048 chunks of 16B
            int row = idx >> 4, c = idx & 15;
            cp_async16(sbase + A_OFF  + row * SSTB + c * 16, asrc + (size_t)row * ROWB + c * 16);
            cp_async16(sbase + B0_OFF + row * SSTB + c * 16, bsrc + (size_t)row * ROWB + c * 16);
        }
        CP_COMMIT();
        CP_WAIT0();
    }
    __syncthreads();

    // x2 per thread: 8 rows (mi 0..3, k2 0..1)
    float x2v[4][2];
    #pragma unroll
    for (int mi = 0; mi < 4; mi++)
        #pragma unroll
        for (int k2 = 0; k2 < 2; k2++)
            x2v[mi][k2] = g_x2[b * NPTS + n0 + wm * 64 + mi * 16 + (ln >> 2) + k2 * 8];

    // ldmatrix base addresses (k-step adds 32 B each)
    uint32_t aaddr[4], baddr[4];
    #pragma unroll
    for (int mi = 0; mi < 4; mi++)
        aaddr[mi] = sbase + A_OFF + (wm * 64 + mi * 16 + (ln & 15)) * SSTB + ((ln >> 4) * 8) * 2;
    #pragma unroll
    for (int ni = 0; ni < 4; ni++)
        baddr[ni] = sbase + B0_OFF + (wn * 32 + ni * 8 + (ln & 7)) * SSTB + (((ln >> 3) & 1) * 8) * 2;

    float rm[8];   // running rowmin per thread (rows mi*2+k2), min over this lane's cols
    #pragma unroll
    for (int r = 0; r < 8; r++) rm[r] = __uint_as_float(INF_BITS);

    for (int t = 0; t < 32; t++) {
        // issue next B tile into the other buffer (overlaps this tile's compute)
        if (t < 31) {
            const unsigned char* bsrc =
                (const unsigned char*)(g_By + (size_t)(b * NPTS + (t + 1) * 128) * DIM);
            uint32_t boff = sbase + (((t + 1) & 1) ? B1_OFF : B0_OFF);
            #pragma unroll
            for (int it = 0; it < 8; it++) {
                int idx = it * 256 + tid;
                int row = idx >> 4, c = idx & 15;
                cp_async16(boff + row * SSTB + c * 16, bsrc + (size_t)row * ROWB + c * 16);
            }
            CP_COMMIT();
        }

        // y2 for this tile's columns (8 per thread), prefetched early
        float y2v[4][2];
        #pragma unroll
        for (int ni = 0; ni < 4; ni++)
            #pragma unroll
            for (int e = 0; e < 2; e++)
                y2v[ni][e] = g_y2[b * NPTS + t * 128 + wn * 32 + ni * 8 + (ln & 3) * 2 + e];

        const uint32_t bsel = (t & 1) ? (B1_OFF - B0_OFF) : 0u;

        float acc[4][4][4];
        #pragma unroll
        for (int mi = 0; mi < 4; mi++)
            #pragma unroll
            for (int ni = 0; ni < 4; ni++)
                #pragma unroll
                for (int k = 0; k < 4; k++) acc[mi][ni][k] = 0.0f;

        // ---- mainloop: K=128 in 8 k-steps ----
        #pragma unroll
        for (int ks = 0; ks < 8; ks++) {
            uint32_t afr[4][4], bfr[4][2];
            #pragma unroll
            for (int mi = 0; mi < 4; mi++) ldsm_x4(afr[mi], aaddr[mi] + ks * 32);
            #pragma unroll
            for (int ni = 0; ni < 4; ni++) ldsm_x2(bfr[ni], baddr[ni] + bsel + ks * 32);
            #pragma unroll
            for (int mi = 0; mi < 4; mi++)
                #pragma unroll
                for (int ni = 0; ni < 4; ni++)
                    mma_f16(acc[mi][ni], afr[mi], bfr[ni]);
        }

        // ---- epilogue: d2, rowmin (regs), colmin (shfl + smem atomics) ----
        float cmv[4][2];
        #pragma unroll
        for (int ni = 0; ni < 4; ni++)
            #pragma unroll
            for (int e = 0; e < 2; e++) cmv[ni][e] = __uint_as_float(INF_BITS);

        #pragma unroll
        for (int mi = 0; mi < 4; mi++)
            #pragma unroll
            for (int ni = 0; ni < 4; ni++)
                #pragma unroll
                for (int k = 0; k < 4; k++) {
                    int k2 = k >> 1, e = k & 1;
                    float d2 = fmaxf(fmaf(-2.0f, acc[mi][ni][k], x2v[mi][k2] + y2v[ni][e]), 0.0f);
                    rm[mi * 2 + k2] = fminf(rm[mi * 2 + k2], d2);
                    cmv[ni][e]      = fminf(cmv[ni][e], d2);
                }

        #pragma unroll
        for (int ni = 0; ni < 4; ni++)
            #pragma unroll
            for (int e = 0; e < 2; e++) {
                float v = cmv[ni][e];
                v = fminf(v, __shfl_xor_sync(0xffffffffu, v, 4));
                v = fminf(v, __shfl_xor_sync(0xffffffffu, v, 8));
                v = fminf(v, __shfl_xor_sync(0xffffffffu, v, 16));
                if (ln < 4)
                    atomicMin(&redC[wn * 32 + ni * 8 + ln * 2 + e], __float_as_uint(v));
            }
        __syncthreads();

        if (tid < 128) {
            atomicMin(&g_colmin[b * NPTS + t * 128 + tid], redC[tid]);
            redC[tid] = INF_BITS;
        }
        if (t < 31) CP_WAIT0();   // next B tile landed
        __syncthreads();
    }

    // ---- final rowmin: fold cols across lanes, then across the 4 N-warps ----
    #pragma unroll
    for (int r = 0; r < 8; r++) {
        float v = rm[r];
        v = fminf(v, __shfl_xor_sync(0xffffffffu, v, 1));
        v = fminf(v, __shfl_xor_sync(0xffffffffu, v, 2));
        if ((ln & 3) == 0) {
            int rowl = wm * 64 + (r >> 1) * 16 + (ln >> 2) + (r & 1) * 8;
            atomicMin(&redR[rowl], __float_as_uint(v));
        }
    }
    __syncthreads();
    if (tid < 128) g_rowmin[b * NPTS + n0 + tid] = redR[tid];
}

// ---------------------------------------------------------------------------
// Kernel 3: per-batch max over union(rowmin, colmin), sqrt, mean.
// ---------------------------------------------------------------------------
__global__ void hd_finalize(float* __restrict__ out) {
    __shared__ float s[256];
    int tid = threadIdx.x;
    float sum = 0.0f;
    for (int b = 0; b < BATCH; b++) {
        float mx = 0.0f;
        for (int i = tid; i < NPTS; i += 256) {
            mx = fmaxf(mx, __uint_as_float(g_rowmin[b * NPTS + i]));
            mx = fmaxf(mx, __uint_as_float(g_colmin[b * NPTS + i]));
        }
        s[tid] = mx;
        __syncthreads();
        for (int st = 128; st > 0; st >>= 1) {
            if (tid < st) s[tid] = fmaxf(s[tid], s[tid + st]);
            __syncthreads();
        }
        if (tid == 0) sum += sqrtf(s[0]);
        __syncthreads();
    }
    if (tid == 0) out[0] = sum * (1.0f / BATCH);
}

// ---------------------------------------------------------------------------
extern "C" void kernel_launch(void* const* d_in, const int* in_sizes, int n_in,
                              void* d_out, int out_size) {
    const float* x = (const float*)d_in[0];
    const float* y = (const float*)d_in[1];
    float* out = (float*)d_out;

    (void)cudaFuncSetAttribute(hd_main, cudaFuncAttributeMaxDynamicSharedMemorySize,
                               SMEM_BYTES);

    hd_prep<<<(2 * BATCH * NPTS * 32) / 256, 256>>>(x, y);
    hd_main<<<BATCH * 32, 256, SMEM_BYTES>>>();
    hd_finalize<<<1, 256>>>(out);
}